// round 1
// baseline (speedup 1.0000x reference)
#include <cuda_runtime.h>
#include <math.h>

#define D   128
#define TQ  64
#define TK  64
#define MAXK 4096

// Normalized keys, stored TRANSPOSED [D][K] so the fused kernel's score-GEMM
// tile loads are coalesced from global and conflict-free into smem.
__device__ __align__(16) float g_knT[(size_t)D * MAXK];

// ---------------------------------------------------------------------------
// Kernel 1: L2-normalize keys, write transposed. One warp per key row.
// ---------------------------------------------------------------------------
__global__ void knorm_kernel(const float* __restrict__ keys, int K) {
    int row  = blockIdx.x * blockDim.y + threadIdx.y;
    if (row >= K) return;
    int lane = threadIdx.x;
    float4 v = reinterpret_cast<const float4*>(keys + (size_t)row * D)[lane];
    float ss = v.x * v.x + v.y * v.y + v.z * v.z + v.w * v.w;
#pragma unroll
    for (int o = 16; o; o >>= 1) ss += __shfl_xor_sync(0xffffffffu, ss, o);
    float s = 1.0f / fmaxf(sqrtf(ss), 1e-12f);
    int d = lane * 4;
    g_knT[(size_t)(d + 0) * K + row] = v.x * s;
    g_knT[(size_t)(d + 1) * K + row] = v.y * s;
    g_knT[(size_t)(d + 2) * K + row] = v.z * s;
    g_knT[(size_t)(d + 3) * K + row] = v.w * s;
}

// ---------------------------------------------------------------------------
// Kernel 2: fused  softmax(q_n @ k_n^T) @ keys   per 64-query CTA.
// No running max needed: scores are cosines in [-1, 1].
// ---------------------------------------------------------------------------
__global__ __launch_bounds__(256, 1)
void fused_kernel(const float* __restrict__ queries,
                  const float* __restrict__ keys,
                  float* __restrict__ out, int K) {
    extern __shared__ float sm[];
    float* Qs     = sm;                       // [D][TQ]   d-major, 8192 f
    float* Ks     = Qs + D * TQ;              // [D][TK]   d-major, 8192 f
    float* Vs     = Ks + D * TK;              // [TK][D]   raw keys, 8192 f
    float* Ps     = Vs + TK * D;              // [TQ][TK+1] probs, 4160 f
    float* qscale = Ps + TQ * (TK + 1);       // [TQ]
    float* red    = qscale + TQ;              // [4][TQ] norm partials
    float* denom  = red + 4 * TQ;             // [TQ]

    const int tid = threadIdx.x;
    const int q0  = blockIdx.x * TQ;

    // ---- Load Q tile transposed into smem + per-row sum of squares ----
    {
        int q    = tid & 63;
        int part = tid >> 6;      // 4 threads per query row
        const float4* qrow =
            reinterpret_cast<const float4*>(queries + (size_t)(q0 + q) * D);
        float ss = 0.f;
#pragma unroll
        for (int i = 0; i < 8; i++) {
            float4 v = qrow[part * 8 + i];
            ss += v.x * v.x + v.y * v.y + v.z * v.z + v.w * v.w;
            int d = part * 32 + i * 4;
            Qs[(d + 0) * TQ + q] = v.x;
            Qs[(d + 1) * TQ + q] = v.y;
            Qs[(d + 2) * TQ + q] = v.z;
            Qs[(d + 3) * TQ + q] = v.w;
        }
        red[part * TQ + q] = ss;
    }
    __syncthreads();
    if (tid < TQ) {
        float ss = red[tid] + red[TQ + tid] + red[2 * TQ + tid] + red[3 * TQ + tid];
        qscale[tid] = 1.0f / fmaxf(sqrtf(ss), 1e-12f);   // fold q-norm into score
    }
    __syncthreads();

    const int ty  = tid >> 4;          // 0..15 query group (GEMM1)
    const int tx  = tid & 15;          // 0..15 key group   (GEMM1)
    const int ty2 = tid >> 5;          // 0..7  query group (GEMM2)
    const int dj  = (tid & 31) * 4;    // d offset          (GEMM2)

    float acc[8][4];
#pragma unroll
    for (int i = 0; i < 8; i++)
#pragma unroll
        for (int j = 0; j < 4; j++) acc[i][j] = 0.f;
    float dpart[4] = {0.f, 0.f, 0.f, 0.f};

    const float qs0 = qscale[ty * 4 + 0];
    const float qs1 = qscale[ty * 4 + 1];
    const float qs2 = qscale[ty * 4 + 2];
    const float qs3 = qscale[ty * 4 + 3];

    for (int k0 = 0; k0 < K; k0 += TK) {
        // ---- Load normalized-key tile (transposed source) + raw-key tile ----
#pragma unroll
        for (int i = 0; i < 8; i++) {
            int idx = tid + i * 256;          // 2048 float4
            int d   = idx >> 4;
            int c4  = idx & 15;
            *reinterpret_cast<float4*>(&Ks[d * TK + c4 * 4]) =
                *reinterpret_cast<const float4*>(&g_knT[(size_t)d * K + k0 + c4 * 4]);
        }
#pragma unroll
        for (int i = 0; i < 8; i++) {
            int idx = tid + i * 256;
            int r   = idx >> 5;
            int c4  = idx & 31;
            *reinterpret_cast<float4*>(&Vs[r * D + c4 * 4]) =
                *reinterpret_cast<const float4*>(&keys[(size_t)(k0 + r) * D + c4 * 4]);
        }
        __syncthreads();

        // ---- GEMM1: S[64x64] = Q_raw . Kn^T  (4x4 per thread) ----
        float c00 = 0, c01 = 0, c02 = 0, c03 = 0;
        float c10 = 0, c11 = 0, c12 = 0, c13 = 0;
        float c20 = 0, c21 = 0, c22 = 0, c23 = 0;
        float c30 = 0, c31 = 0, c32 = 0, c33 = 0;
#pragma unroll 4
        for (int d = 0; d < D; d++) {
            float4 a = *reinterpret_cast<const float4*>(&Qs[d * TQ + ty * 4]);
            float4 b = *reinterpret_cast<const float4*>(&Ks[d * TK + tx * 4]);
            c00 += a.x * b.x; c01 += a.x * b.y; c02 += a.x * b.z; c03 += a.x * b.w;
            c10 += a.y * b.x; c11 += a.y * b.y; c12 += a.y * b.z; c13 += a.y * b.w;
            c20 += a.z * b.x; c21 += a.z * b.y; c22 += a.z * b.z; c23 += a.z * b.w;
            c30 += a.w * b.x; c31 += a.w * b.y; c32 += a.w * b.z; c33 += a.w * b.w;
        }

        // ---- exp (no max needed, scores in [-1,1]); P to smem; denom partials ----
        {
            float p;
            float* prow;
            prow = &Ps[(ty * 4 + 0) * (TK + 1) + tx * 4];
            p = __expf(c00 * qs0); dpart[0] += p; prow[0] = p;
            p = __expf(c01 * qs0); dpart[0] += p; prow[1] = p;
            p = __expf(c02 * qs0); dpart[0] += p; prow[2] = p;
            p = __expf(c03 * qs0); dpart[0] += p; prow[3] = p;
            prow = &Ps[(ty * 4 + 1) * (TK + 1) + tx * 4];
            p = __expf(c10 * qs1); dpart[1] += p; prow[0] = p;
            p = __expf(c11 * qs1); dpart[1] += p; prow[1] = p;
            p = __expf(c12 * qs1); dpart[1] += p; prow[2] = p;
            p = __expf(c13 * qs1); dpart[1] += p; prow[3] = p;
            prow = &Ps[(ty * 4 + 2) * (TK + 1) + tx * 4];
            p = __expf(c20 * qs2); dpart[2] += p; prow[0] = p;
            p = __expf(c21 * qs2); dpart[2] += p; prow[1] = p;
            p = __expf(c22 * qs2); dpart[2] += p; prow[2] = p;
            p = __expf(c23 * qs2); dpart[2] += p; prow[3] = p;
            prow = &Ps[(ty * 4 + 3) * (TK + 1) + tx * 4];
            p = __expf(c30 * qs3); dpart[3] += p; prow[0] = p;
            p = __expf(c31 * qs3); dpart[3] += p; prow[1] = p;
            p = __expf(c32 * qs3); dpart[3] += p; prow[2] = p;
            p = __expf(c33 * qs3); dpart[3] += p; prow[3] = p;
        }
        __syncthreads();

        // ---- GEMM2: acc[64x128] += P . V_raw  (8q x 4d per thread) ----
#pragma unroll 4
        for (int kk = 0; kk < TK; kk++) {
            float4 v = *reinterpret_cast<const float4*>(&Vs[kk * D + dj]);
#pragma unroll
            for (int i = 0; i < 8; i++) {
                float p = Ps[(ty2 * 8 + i) * (TK + 1) + kk];
                acc[i][0] += p * v.x;
                acc[i][1] += p * v.y;
                acc[i][2] += p * v.z;
                acc[i][3] += p * v.w;
            }
        }
        __syncthreads();   // before next tile's loads overwrite Ks/Vs/Ps
    }

    // ---- Reduce denominators across the 16 tx lanes of each query row ----
#pragma unroll
    for (int i = 0; i < 4; i++) {
        float s = dpart[i];
#pragma unroll
        for (int o = 8; o; o >>= 1) s += __shfl_xor_sync(0xffffffffu, s, o);
        if (tx == 0) denom[ty * 4 + i] = s;
    }
    __syncthreads();

    // ---- Normalize and write out ----
#pragma unroll
    for (int i = 0; i < 8; i++) {
        int   q   = ty2 * 8 + i;
        float inv = 1.0f / denom[q];
        float4 o4 = make_float4(acc[i][0] * inv, acc[i][1] * inv,
                                acc[i][2] * inv, acc[i][3] * inv);
        *reinterpret_cast<float4*>(&out[(size_t)(q0 + q) * D + dj]) = o4;
    }
}

// ---------------------------------------------------------------------------
extern "C" void kernel_launch(void* const* d_in, const int* in_sizes, int n_in,
                              void* d_out, int out_size) {
    const float* queries = (const float*)d_in[0];
    const float* keys    = (const float*)d_in[1];
    float*       out     = (float*)d_out;

    int N = in_sizes[0] / D;
    int K = in_sizes[1] / D;

    const int smem_bytes = (D * TQ + D * TK + TK * D + TQ * (TK + 1) + TQ + 4 * TQ + TQ)
                           * (int)sizeof(float);   // 116480 B
    cudaFuncSetAttribute(fused_kernel,
                         cudaFuncAttributeMaxDynamicSharedMemorySize, smem_bytes);

    knorm_kernel<<<(K + 7) / 8, dim3(32, 8)>>>(keys, K);
    fused_kernel<<<N / TQ, 256, smem_bytes>>>(queries, keys, out, K);
}

// round 4
// speedup vs baseline: 4.0911x; 4.0911x over previous
#include <cuda_runtime.h>
#include <cstdint>
#include <math.h>

#define D    128
#define TQ   128
#define TK   64
#define KMAX 4096

// Strides (floats) chosen for conflict-free fragment LDS
#define S1 136   // Qs  [d][row]
#define S2 72    // Ks  [d][key]
#define S4 68    // Vs  [d][key]
#define S3 136   // Ps  [key][row]

// SMEM byte offsets
#define SM_Q   0
#define SM_K   69632                   // 128*136*4
#define SM_V0  106496                  // +128*72*4
#define SM_V1  141312                  // +128*68*4
#define SM_P   176128                  // +128*68*4
#define SM_DS  210944                  // +64*136*4
#define SMEM_TOTAL (210944 + 1024)

// Preprocessed keys (tf32-rounded fp32), both stored [d][key]
__device__ __align__(16) float g_kn [(size_t)D * KMAX];  // normalized (score side)
__device__ __align__(16) float g_ktT[(size_t)D * KMAX];  // raw (value side)

// ---------------- helpers ----------------
__device__ __forceinline__ uint32_t smem_u32(const void* p) {
    uint32_t a;
    asm("{ .reg .u64 t; cvta.to.shared.u64 t, %1; cvt.u32.u64 %0, t; }" : "=r"(a) : "l"(p));
    return a;
}
__device__ __forceinline__ void cp16(uint32_t s, const void* g) {
    asm volatile("cp.async.cg.shared.global [%0], [%1], 16;\n" :: "r"(s), "l"(g));
}
__device__ __forceinline__ void cp_commit() { asm volatile("cp.async.commit_group;\n" ::: "memory"); }
__device__ __forceinline__ void cp_wait0()  { asm volatile("cp.async.wait_group 0;\n" ::: "memory"); }

__device__ __forceinline__ uint32_t to_tf32(float f) {
    uint32_t r;
    asm("cvt.rna.tf32.f32 %0, %1;" : "=r"(r) : "f"(f));
    return r;
}
__device__ __forceinline__ void mma8(float* d,
                                     uint32_t a0, uint32_t a1, uint32_t a2, uint32_t a3,
                                     uint32_t b0, uint32_t b1) {
    asm volatile(
        "mma.sync.aligned.m16n8k8.row.col.f32.tf32.tf32.f32 "
        "{%0,%1,%2,%3},{%4,%5,%6,%7},{%8,%9},{%0,%1,%2,%3};\n"
        : "+f"(d[0]), "+f"(d[1]), "+f"(d[2]), "+f"(d[3])
        : "r"(a0), "r"(a1), "r"(a2), "r"(a3), "r"(b0), "r"(b1));
}

// ---------------------------------------------------------------------------
// Prep: per key row — normalize (score copy) + keep raw (value copy),
// both tf32-rounded, both stored transposed [d][key].
// ---------------------------------------------------------------------------
__global__ void prep_kernel(const float* __restrict__ keys, int K) {
    int row = blockIdx.x * blockDim.y + threadIdx.y;
    if (row >= K) return;
    int lane = threadIdx.x;
    float4 v = reinterpret_cast<const float4*>(keys + (size_t)row * D)[lane];
    float ss = v.x * v.x + v.y * v.y + v.z * v.z + v.w * v.w;
#pragma unroll
    for (int o = 16; o; o >>= 1) ss += __shfl_xor_sync(0xffffffffu, ss, o);
    float s = 1.0f / fmaxf(sqrtf(ss), 1e-12f);
    int d = lane * 4;
    float vv[4] = {v.x, v.y, v.z, v.w};
#pragma unroll
    for (int c = 0; c < 4; c++) {
        g_kn [(size_t)(d + c) * K + row] = __uint_as_float(to_tf32(vv[c] * s));
        g_ktT[(size_t)(d + c) * K + row] = __uint_as_float(to_tf32(vv[c]));
    }
}

// ---------------------------------------------------------------------------
// Fused flash kernel: 128 queries/CTA, tf32 mma.sync, K in 64-key tiles.
// ---------------------------------------------------------------------------
__global__ __launch_bounds__(256, 1)
void fused_mma(const float* __restrict__ queries, float* __restrict__ out, int K) {
    extern __shared__ __align__(16) float sm[];
    const uint32_t sb = smem_u32(sm);
    const int tid  = threadIdx.x;
    const int w    = tid >> 5;
    const int lane = tid & 31;
    const int g    = lane >> 2;      // 0..7
    const int tig  = lane & 3;       // 0..3
    const int mg   = w >> 1;         // 0..3 : 32-row stripe
    const int ng   = w & 1;          // 0..1 : n-half
    const int q0   = blockIdx.x * TQ;
    const int niter = K / TK;

    float* Qs = sm;
    float* Ks = sm + SM_K  / 4;
    float* Ps = sm + SM_P  / 4;
    float* DS = sm + SM_DS / 4;

    // ---- Load Q: normalize rows, cvt tf32, store transposed [d][row] ----
    {
        int row  = tid >> 1;
        int part = tid & 1;
        const float4* qr = reinterpret_cast<const float4*>(
            queries + (size_t)(q0 + row) * D + part * 64);
        float ss = 0.f;
#pragma unroll
        for (int i = 0; i < 16; i++) {
            float4 v = qr[i];
            ss += v.x * v.x + v.y * v.y + v.z * v.z + v.w * v.w;
        }
        ss += __shfl_xor_sync(0xffffffffu, ss, 1);
        float s = 1.0f / fmaxf(sqrtf(ss), 1e-12f);
#pragma unroll
        for (int i = 0; i < 16; i++) {
            float4 v = qr[i];
            int d = part * 64 + i * 4;
            Qs[(d + 0) * S1 + row] = __uint_as_float(to_tf32(v.x * s));
            Qs[(d + 1) * S1 + row] = __uint_as_float(to_tf32(v.y * s));
            Qs[(d + 2) * S1 + row] = __uint_as_float(to_tf32(v.z * s));
            Qs[(d + 3) * S1 + row] = __uint_as_float(to_tf32(v.w * s));
        }
    }

    // ---- Prologue: tile 0 of Kn and V ----
    {
        const char* kg = reinterpret_cast<const char*>(g_kn);
        const char* vg = reinterpret_cast<const char*>(g_ktT);
#pragma unroll
        for (int u = 0; u < 8; u++) {
            int id = u * 256 + tid;
            int d = id >> 4, c = id & 15;
            cp16(sb + SM_K + d * (S2 * 4) + c * 16, kg + (size_t)d * (KMAX * 4) + c * 16);
        }
#pragma unroll
        for (int u = 0; u < 8; u++) {
            int id = u * 256 + tid;
            int d = id >> 4, c = id & 15;
            cp16(sb + SM_V0 + d * (S4 * 4) + c * 16, vg + (size_t)d * (KMAX * 4) + c * 16);
        }
        cp_commit();
    }

    // Per-thread operand base pointers (conflict-free layouts)
    const float* qp = Qs + tig * S1 + 32 * mg + g;          // A (GEMM1)
    const float* kp = Ks + tig * S2 + 32 * ng + g;          // B (GEMM1)
    const float* pp = Ps + tig * S3 + 32 * mg + g;          // A (GEMM2)

    float Oa[16][4];                    // O accum: [mt(2) * nt(8)][4]
#pragma unroll
    for (int i = 0; i < 16; i++)
#pragma unroll
        for (int j = 0; j < 4; j++) Oa[i][j] = 0.f;
    float dacc[4] = {0.f, 0.f, 0.f, 0.f};

    for (int it = 0; it < niter; it++) {
        const float* Vs = sm + ((it & 1) ? SM_V1 : SM_V0) / 4;
        const float* vp = Vs + (64 * ng + g) * S4 + tig;    // B (GEMM2)

        cp_wait0();
        __syncthreads();   // tiles ready; prev iter's GEMM2 done (Ps safe to rewrite)

        // ---- GEMM1: S(32x32 per warp) = Qn . Kn^T ----
        float Sa[8][4];
#pragma unroll
        for (int i = 0; i < 8; i++)
#pragma unroll
            for (int j = 0; j < 4; j++) Sa[i][j] = 0.f;
#pragma unroll
        for (int s = 0; s < 16; s++) {
            const float* q = qp + s * 8 * S1;
            const float* k = kp + s * 8 * S2;
            uint32_t a[2][4];
#pragma unroll
            for (int mt = 0; mt < 2; mt++) {
                a[mt][0] = __float_as_uint(q[mt * 16]);
                a[mt][1] = __float_as_uint(q[mt * 16 + 8]);
                a[mt][2] = __float_as_uint(q[4 * S1 + mt * 16]);
                a[mt][3] = __float_as_uint(q[4 * S1 + mt * 16 + 8]);
            }
#pragma unroll
            for (int nt = 0; nt < 4; nt++) {
                uint32_t b0 = __float_as_uint(k[nt * 8]);
                uint32_t b1 = __float_as_uint(k[4 * S2 + nt * 8]);
                mma8(Sa[nt],     a[0][0], a[0][1], a[0][2], a[0][3], b0, b1);
                mma8(Sa[4 + nt], a[1][0], a[1][1], a[1][2], a[1][3], b0, b1);
            }
        }
        __syncthreads();   // all warps done reading Ks -> safe to refill

        // ---- Prefetch next tile (Ks in place; V into alternate buffer) ----
        if (it + 1 < niter) {
            const int k0 = (it + 1) * TK;
            const char* kg = reinterpret_cast<const char*>(g_kn)  + (size_t)k0 * 4;
            const char* vg = reinterpret_cast<const char*>(g_ktT) + (size_t)k0 * 4;
            const uint32_t vdst = (it & 1) ? SM_V0 : SM_V1;
#pragma unroll
            for (int u = 0; u < 8; u++) {
                int id = u * 256 + tid;
                int d = id >> 4, c = id & 15;
                cp16(sb + SM_K + d * (S2 * 4) + c * 16, kg + (size_t)d * (KMAX * 4) + c * 16);
            }
#pragma unroll
            for (int u = 0; u < 8; u++) {
                int id = u * 256 + tid;
                int d = id >> 4, c = id & 15;
                cp16(sb + vdst + d * (S4 * 4) + c * 16, vg + (size_t)d * (KMAX * 4) + c * 16);
            }
            cp_commit();
        }

        // ---- softmax: p = exp(s) (cosine scores, no max pass); P -> smem tf32 ----
#pragma unroll
        for (int mt = 0; mt < 2; mt++)
#pragma unroll
            for (int nt = 0; nt < 4; nt++) {
                float* f = Sa[mt * 4 + nt];
                int keyb = 32 * ng + 8 * nt + 2 * tig;
#pragma unroll
                for (int e = 0; e < 4; e++) {
                    float p = __expf(f[e]);
                    dacc[mt * 2 + (e >> 1)] += p;
                    int key = keyb + (e & 1);
                    int row = 32 * mg + 16 * mt + g + ((e >> 1) << 3);
                    Ps[key * S3 + row] = __uint_as_float(to_tf32(p));
                }
            }
        __syncthreads();   // P visible

        // ---- GEMM2: O(32x64 per warp) += P . V ----
#pragma unroll
        for (int s = 0; s < 8; s++) {
            const float* p = pp + s * 8 * S3;
            const float* v = vp + s * 8;
            uint32_t a[2][4];
#pragma unroll
            for (int mt = 0; mt < 2; mt++) {
                a[mt][0] = __float_as_uint(p[mt * 16]);
                a[mt][1] = __float_as_uint(p[mt * 16 + 8]);
                a[mt][2] = __float_as_uint(p[4 * S3 + mt * 16]);
                a[mt][3] = __float_as_uint(p[4 * S3 + mt * 16 + 8]);
            }
#pragma unroll
            for (int nt = 0; nt < 8; nt++) {
                uint32_t b0 = __float_as_uint(v[nt * 8 * S4]);
                uint32_t b1 = __float_as_uint(v[nt * 8 * S4 + 4]);
                mma8(Oa[nt],     a[0][0], a[0][1], a[0][2], a[0][3], b0, b1);
                mma8(Oa[8 + nt], a[1][0], a[1][1], a[1][2], a[1][3], b0, b1);
            }
        }
    }

    // ---- denominators: reduce over tig quads, combine n-halves via smem ----
#pragma unroll
    for (int r = 0; r < 4; r++) {
        dacc[r] += __shfl_xor_sync(0xffffffffu, dacc[r], 1);
        dacc[r] += __shfl_xor_sync(0xffffffffu, dacc[r], 2);
    }
    __syncthreads();
    if (tig == 0) {
#pragma unroll
        for (int r = 0; r < 4; r++) {
            int row = 32 * mg + 16 * (r >> 1) + g + ((r & 1) << 3);
            DS[ng * 128 + row] = dacc[r];
        }
    }
    __syncthreads();

    // ---- epilogue: out = O / denom ----
#pragma unroll
    for (int mt = 0; mt < 2; mt++) {
#pragma unroll
        for (int hi = 0; hi < 2; hi++) {
            int row = 32 * mg + 16 * mt + g + hi * 8;
            float inv = 1.0f / (DS[row] + DS[128 + row]);
            float* orow = out + (size_t)(q0 + row) * D + 64 * ng + 2 * tig;
#pragma unroll
            for (int nt = 0; nt < 8; nt++) {
                float2 o = make_float2(Oa[mt * 8 + nt][hi * 2] * inv,
                                       Oa[mt * 8 + nt][hi * 2 + 1] * inv);
                *reinterpret_cast<float2*>(orow + nt * 8) = o;
            }
        }
    }
}

// ---------------------------------------------------------------------------
extern "C" void kernel_launch(void* const* d_in, const int* in_sizes, int n_in,
                              void* d_out, int out_size) {
    const float* queries = (const float*)d_in[0];
    const float* keys    = (const float*)d_in[1];
    float*       out     = (float*)d_out;

    int N = in_sizes[0] / D;
    int K = in_sizes[1] / D;

    cudaFuncSetAttribute(fused_mma, cudaFuncAttributeMaxDynamicSharedMemorySize, SMEM_TOTAL);

    prep_kernel<<<(K + 7) / 8, dim3(32, 8)>>>(keys, K);
    fused_mma<<<N / TQ, 256, SMEM_TOTAL>>>(queries, out, K);
}

// round 6
// speedup vs baseline: 4.3376x; 1.0602x over previous
#include <cuda_runtime.h>
#include <cstdint>
#include <math.h>

#define D    128
#define TQ   128
#define TK   64
#define KMAX 4096

// Strides (floats) chosen for conflict-free fragment LDS
#define S1 136   // Qs  [d][row]
#define S2 72    // Ks  [d][key]
#define S4 68    // Vs  [d][key]

// SMEM byte offsets
#define SM_Q   0                       // 128*136*4 = 69632
#define SM_K0  69632                   // 128*72*4  = 36864
#define SM_K1  106496
#define SM_V0  143360                  // 128*68*4  = 34816
#define SM_V1  178176
#define SM_DS  212992                  // 1024
#define SMEM_TOTAL 214016

// Preprocessed keys (tf32-rounded fp32), both stored [d][key]
__device__ __align__(16) float g_kn [(size_t)D * KMAX];  // normalized (score side)
__device__ __align__(16) float g_ktT[(size_t)D * KMAX];  // raw (value side)

// ---------------- helpers ----------------
__device__ __forceinline__ uint32_t smem_u32(const void* p) {
    uint32_t a;
    asm("{ .reg .u64 t; cvta.to.shared.u64 t, %1; cvt.u32.u64 %0, t; }" : "=r"(a) : "l"(p));
    return a;
}
__device__ __forceinline__ void cp16(uint32_t s, const void* g) {
    asm volatile("cp.async.cg.shared.global [%0], [%1], 16;\n" :: "r"(s), "l"(g));
}
__device__ __forceinline__ void cp_commit() { asm volatile("cp.async.commit_group;\n" ::: "memory"); }
__device__ __forceinline__ void cp_wait0()  { asm volatile("cp.async.wait_group 0;\n" ::: "memory"); }

__device__ __forceinline__ uint32_t to_tf32(float f) {
    uint32_t r;
    asm("cvt.rna.tf32.f32 %0, %1;" : "=r"(r) : "f"(f));
    return r;
}
__device__ __forceinline__ void mma8(float* d,
                                     uint32_t a0, uint32_t a1, uint32_t a2, uint32_t a3,
                                     uint32_t b0, uint32_t b1) {
    asm volatile(
        "mma.sync.aligned.m16n8k8.row.col.f32.tf32.tf32.f32 "
        "{%0,%1,%2,%3},{%4,%5,%6,%7},{%8,%9},{%0,%1,%2,%3};\n"
        : "+f"(d[0]), "+f"(d[1]), "+f"(d[2]), "+f"(d[3])
        : "r"(a0), "r"(a1), "r"(a2), "r"(a3), "r"(b0), "r"(b1));
}

// One 64-key tile of Kn + V -> smem (cp.async), 16 chunks of 16B per d-row
__device__ __forceinline__ void load_tile(uint32_t sb, int tid, int k0,
                                          uint32_t kdst, uint32_t vdst) {
    const char* kg = reinterpret_cast<const char*>(g_kn)  + (size_t)k0 * 4;
    const char* vg = reinterpret_cast<const char*>(g_ktT) + (size_t)k0 * 4;
#pragma unroll
    for (int u = 0; u < 8; u++) {
        int id = u * 256 + tid;
        int d = id >> 4, c = id & 15;
        cp16(sb + kdst + d * (S2 * 4) + c * 16, kg + (size_t)d * (KMAX * 4) + c * 16);
    }
#pragma unroll
    for (int u = 0; u < 8; u++) {
        int id = u * 256 + tid;
        int d = id >> 4, c = id & 15;
        cp16(sb + vdst + d * (S4 * 4) + c * 16, vg + (size_t)d * (KMAX * 4) + c * 16);
    }
}

// ---------------------------------------------------------------------------
// Prep: per key row — normalized (score) + raw (value) copies, tf32-rounded,
// both stored transposed [d][key].
// ---------------------------------------------------------------------------
__global__ void prep_kernel(const float* __restrict__ keys, int K) {
    int row = blockIdx.x * blockDim.y + threadIdx.y;
    if (row >= K) return;
    int lane = threadIdx.x;
    float4 v = reinterpret_cast<const float4*>(keys + (size_t)row * D)[lane];
    float ss = v.x * v.x + v.y * v.y + v.z * v.z + v.w * v.w;
#pragma unroll
    for (int o = 16; o; o >>= 1) ss += __shfl_xor_sync(0xffffffffu, ss, o);
    float s = 1.0f / fmaxf(sqrtf(ss), 1e-12f);
    int d = lane * 4;
    float vv[4] = {v.x, v.y, v.z, v.w};
#pragma unroll
    for (int c = 0; c < 4; c++) {
        g_kn [(size_t)(d + c) * K + row] = __uint_as_float(to_tf32(vv[c] * s));
        g_ktT[(size_t)(d + c) * K + row] = __uint_as_float(to_tf32(vv[c]));
    }
}

// ---------------------------------------------------------------------------
// Fused flash kernel: 128 queries/CTA, tf32 mma.sync, register-resident P.
// Warp (mg,ng): S rows [32mg,32mg+32) x keys [32ng,32ng+32) of each 64-key
// tile; GEMM2 accumulates private O[32x128] over its own key chunk; ng pairs
// are summed in the epilogue.
// ---------------------------------------------------------------------------
__global__ __launch_bounds__(256, 1)
void fused_mma(const float* __restrict__ queries, float* __restrict__ out, int K) {
    extern __shared__ __align__(16) float sm[];
    const uint32_t sb = smem_u32(sm);
    const int tid  = threadIdx.x;
    const int w    = tid >> 5;
    const int lane = tid & 31;
    const int g    = lane >> 2;      // 0..7
    const int tig  = lane & 3;       // 0..3
    const int mg   = w >> 1;         // 0..3 : 32-row stripe
    const int ng   = w & 1;          // 0..1 : 32-key chunk within tile
    const int q0   = blockIdx.x * TQ;
    const int niter = K / TK;

    float* Qs = sm;
    float* DS = sm + SM_DS / 4;

    // ---- Prologue: tile 0 of Kn and V ----
    load_tile(sb, tid, 0, SM_K0, SM_V0);
    cp_commit();

    // ---- Load Q: normalize rows, cvt tf32, store transposed [d][row] ----
    {
        int row  = tid >> 1;
        int part = tid & 1;
        const float4* qr = reinterpret_cast<const float4*>(
            queries + (size_t)(q0 + row) * D + part * 64);
        float ss = 0.f;
#pragma unroll
        for (int i = 0; i < 16; i++) {
            float4 v = qr[i];
            ss += v.x * v.x + v.y * v.y + v.z * v.z + v.w * v.w;
        }
        ss += __shfl_xor_sync(0xffffffffu, ss, 1);
        float s = 1.0f / fmaxf(sqrtf(ss), 1e-12f);
#pragma unroll
        for (int i = 0; i < 16; i++) {
            float4 v = qr[i];
            int d = part * 64 + i * 4;
            Qs[(d + 0) * S1 + row] = __uint_as_float(to_tf32(v.x * s));
            Qs[(d + 1) * S1 + row] = __uint_as_float(to_tf32(v.y * s));
            Qs[(d + 2) * S1 + row] = __uint_as_float(to_tf32(v.z * s));
            Qs[(d + 3) * S1 + row] = __uint_as_float(to_tf32(v.w * s));
        }
    }

    const float* qp = Qs + tig * S1 + 32 * mg + g;      // A (GEMM1)

    float Oa[32][4];                  // private O: [mt*16+nt][4], rows 32mg..,
#pragma unroll                         // d = 8nt+{2tig,2tig+1}, rows g/g+8
    for (int i = 0; i < 32; i++)
#pragma unroll
        for (int j = 0; j < 4; j++) Oa[i][j] = 0.f;
    float dacc[4] = {0.f, 0.f, 0.f, 0.f};

    const int src_a = (lane & 28) | (tig >> 1);   // quad shuffle sources
    const int src_b = src_a + 2;
    const bool odd  = (tig & 1);

    for (int it = 0; it < niter; it++) {
        cp_wait0();                    // tile it landed (only group outstanding)
        __syncthreads();               // visible to all; buffers of it-1 free

        if (it + 1 < niter)            // prefetch overlaps this body
            load_tile(sb, tid, (it + 1) * TK,
                      ((it + 1) & 1) ? SM_K1 : SM_K0,
                      ((it + 1) & 1) ? SM_V1 : SM_V0);
        cp_commit();

        const float* Ks = sm + (((it & 1) ? SM_K1 : SM_K0) >> 2);
        const float* Vs = sm + (((it & 1) ? SM_V1 : SM_V0) >> 2);
        const float* kp = Ks + tig * S2 + 32 * ng + g;

        // ---- GEMM1: S(32x32 per warp) = Qn . Kn^T ----
        float Sa[8][4];
#pragma unroll
        for (int i = 0; i < 8; i++)
#pragma unroll
            for (int j = 0; j < 4; j++) Sa[i][j] = 0.f;
#pragma unroll
        for (int s = 0; s < 16; s++) {
            const float* q = qp + s * 8 * S1;
            const float* k = kp + s * 8 * S2;
            uint32_t a[2][4];
#pragma unroll
            for (int mt = 0; mt < 2; mt++) {
                a[mt][0] = __float_as_uint(q[mt * 16]);
                a[mt][1] = __float_as_uint(q[mt * 16 + 8]);
                a[mt][2] = __float_as_uint(q[4 * S1 + mt * 16]);
                a[mt][3] = __float_as_uint(q[4 * S1 + mt * 16 + 8]);
            }
#pragma unroll
            for (int nt = 0; nt < 4; nt++) {
                uint32_t b0 = __float_as_uint(k[nt * 8]);
                uint32_t b1 = __float_as_uint(k[4 * S2 + nt * 8]);
                mma8(Sa[nt],     a[0][0], a[0][1], a[0][2], a[0][3], b0, b1);
                mma8(Sa[4 + nt], a[1][0], a[1][1], a[1][2], a[1][3], b0, b1);
            }
        }

        // ---- softmax in registers (cosine scores => no max pass) ----
#pragma unroll
        for (int mt = 0; mt < 2; mt++)
#pragma unroll
            for (int nt = 0; nt < 4; nt++) {
                float* f = Sa[mt * 4 + nt];
#pragma unroll
                for (int e = 0; e < 4; e++) {
                    float p = __expf(f[e]);
                    dacc[mt * 2 + (e >> 1)] += p;
                    f[e] = __uint_as_float(to_tf32(p));
                }
            }

        // ---- GEMM2: O(32x128 private) += P(regs) . V over this warp's keys ----
#pragma unroll
        for (int s = 0; s < 4; s++) {          // k-step = accum column block s
            uint32_t A[2][4];
#pragma unroll
            for (int mt = 0; mt < 2; mt++) {
                const float* dreg = Sa[mt * 4 + s];
                float x0 = __shfl_sync(0xffffffffu, dreg[0], src_a);
                float x1 = __shfl_sync(0xffffffffu, dreg[1], src_a);
                float x2 = __shfl_sync(0xffffffffu, dreg[2], src_a);
                float x3 = __shfl_sync(0xffffffffu, dreg[3], src_a);
                float y0 = __shfl_sync(0xffffffffu, dreg[0], src_b);
                float y1 = __shfl_sync(0xffffffffu, dreg[1], src_b);
                float y2 = __shfl_sync(0xffffffffu, dreg[2], src_b);
                float y3 = __shfl_sync(0xffffffffu, dreg[3], src_b);
                A[mt][0] = __float_as_uint(odd ? x1 : x0);   // row g,   col tig
                A[mt][1] = __float_as_uint(odd ? x3 : x2);   // row g+8, col tig
                A[mt][2] = __float_as_uint(odd ? y1 : y0);   // row g,   col tig+4
                A[mt][3] = __float_as_uint(odd ? y3 : y2);   // row g+8, col tig+4
            }
            const float* v = Vs + g * S4 + tig + 32 * ng + 8 * s;
#pragma unroll
            for (int nt = 0; nt < 16; nt++) {
                uint32_t b0 = __float_as_uint(v[(8 * nt) * S4]);
                uint32_t b1 = __float_as_uint(v[(8 * nt) * S4 + 4]);
                mma8(Oa[nt],      A[0][0], A[0][1], A[0][2], A[0][3], b0, b1);
                mma8(Oa[16 + nt], A[1][0], A[1][1], A[1][2], A[1][3], b0, b1);
            }
        }
    }

    __syncthreads();   // loop done everywhere; Qs region free for reuse

    // ---- denominators: quad-reduce, publish per (ng, row) ----
#pragma unroll
    for (int r = 0; r < 4; r++) {
        dacc[r] += __shfl_xor_sync(0xffffffffu, dacc[r], 1);
        dacc[r] += __shfl_xor_sync(0xffffffffu, dacc[r], 2);
    }
    if (tig == 0) {
#pragma unroll
        for (int r = 0; r < 4; r++) {
            int row = 32 * mg + 16 * (r >> 1) + g + ((r & 1) << 3);
            DS[ng * 128 + row] = dacc[r];
        }
    }

    // ---- O pair-reduction: ng=0 publishes, ng=1 combines + writes ----
    float* Eb = sm + mg * 4224 + lane * 132;   // padded: 33*4 floats/lane
    if (ng == 0) {
#pragma unroll
        for (int j = 0; j < 32; j++)
            *reinterpret_cast<float4*>(Eb + j * 4) =
                *reinterpret_cast<const float4*>(Oa[j]);
    }
    __syncthreads();

    if (ng == 1) {
#pragma unroll
        for (int mt = 0; mt < 2; mt++) {
            int row0 = 32 * mg + 16 * mt + g;
            float i0 = 1.0f / (DS[row0] + DS[128 + row0]);
            float i1 = 1.0f / (DS[row0 + 8] + DS[128 + row0 + 8]);
#pragma unroll
            for (int nt = 0; nt < 16; nt++) {
                int j = mt * 16 + nt;
                float4 p = *reinterpret_cast<const float4*>(Eb + j * 4);
                float2 o0 = make_float2((Oa[j][0] + p.x) * i0,
                                        (Oa[j][1] + p.y) * i0);
                float2 o1 = make_float2((Oa[j][2] + p.z) * i1,
                                        (Oa[j][3] + p.w) * i1);
                float* base = out + (size_t)(q0 + row0) * D + 8 * nt + 2 * tig;
                *reinterpret_cast<float2*>(base)         = o0;
                *reinterpret_cast<float2*>(base + 8 * D) = o1;
            }
        }
    }
}

// ---------------------------------------------------------------------------
extern "C" void kernel_launch(void* const* d_in, const int* in_sizes, int n_in,
                              void* d_out, int out_size) {
    const float* queries = (const float*)d_in[0];
    const float* keys    = (const float*)d_in[1];
    float*       out     = (float*)d_out;

    int N = in_sizes[0] / D;
    int K = in_sizes[1] / D;

    cudaFuncSetAttribute(fused_mma, cudaFuncAttributeMaxDynamicSharedMemorySize, SMEM_TOTAL);

    prep_kernel<<<(K + 7) / 8, dim3(32, 8)>>>(keys, K);
    fused_mma<<<N / TQ, 256, SMEM_TOTAL>>>(queries, out, K);
}

// round 7
// speedup vs baseline: 5.0056x; 1.1540x over previous
#include <cuda_runtime.h>
#include <cstdint>
#include <math.h>

#define D    128
#define TQ   128
#define TK   64
#define KMAX 4096
#define NT64 (KMAX / 64)

// Fragment-packed key operands: 8192 floats (32KB) per 64-key tile.
// KF: [tile][ng(2)][s(16)][j(2)][lane(32)][4]   (scores, normalized keys)
// VF: [tile][ng(2)][s(4)][j(8)][lane(32)][4]    (values, raw keys)
__device__ __align__(16) float g_kf[(size_t)NT64 * 8192];
__device__ __align__(16) float g_vf[(size_t)NT64 * 8192];

// SMEM layout (bytes)
#define SM_QF  0          // 65536 : packed Q fragments [(2mg+mt)*16+s][lane][4]
#define SM_K0  65536
#define SM_V0  98304
#define SM_K1  131072
#define SM_V1  163840
#define SM_QT  131072     // Qtmp overlay on K1+V1 (+pad): 128*132*4 = 67584
#define SM_DS  198656     // 1024
#define SMEM_TOTAL 199680

// ---------------- helpers ----------------
__device__ __forceinline__ uint32_t smem_u32(const void* p) {
    uint32_t a;
    asm("{ .reg .u64 t; cvta.to.shared.u64 t, %1; cvt.u32.u64 %0, t; }" : "=r"(a) : "l"(p));
    return a;
}
__device__ __forceinline__ void cp16(uint32_t s, const void* g) {
    asm volatile("cp.async.cg.shared.global [%0], [%1], 16;\n" :: "r"(s), "l"(g));
}
__device__ __forceinline__ void cp_commit() { asm volatile("cp.async.commit_group;\n" ::: "memory"); }
__device__ __forceinline__ void cp_wait0()  { asm volatile("cp.async.wait_group 0;\n" ::: "memory"); }

__device__ __forceinline__ uint32_t to_tf32(float f) {
    uint32_t r;
    asm("cvt.rna.tf32.f32 %0, %1;" : "=r"(r) : "f"(f));
    return r;
}
__device__ __forceinline__ float to_tf32f(float f) { return __uint_as_float(to_tf32(f)); }

__device__ __forceinline__ void mma8(float* d,
                                     uint32_t a0, uint32_t a1, uint32_t a2, uint32_t a3,
                                     uint32_t b0, uint32_t b1) {
    asm volatile(
        "mma.sync.aligned.m16n8k8.row.col.f32.tf32.tf32.f32 "
        "{%0,%1,%2,%3},{%4,%5,%6,%7},{%8,%9},{%0,%1,%2,%3};\n"
        : "+f"(d[0]), "+f"(d[1]), "+f"(d[2]), "+f"(d[3])
        : "r"(a0), "r"(a1), "r"(a2), "r"(a3), "r"(b0), "r"(b1));
}
#define MMA8F(dst, A, b0, b1) \
    mma8(dst, __float_as_uint((A).x), __float_as_uint((A).y), \
              __float_as_uint((A).z), __float_as_uint((A).w), \
              __float_as_uint(b0), __float_as_uint(b1))

// Linear 32KB tile copy: 2048 x 16B chunks, 256 threads
__device__ __forceinline__ void load_tile(uint32_t sb, int tid, int t,
                                          uint32_t kdst, uint32_t vdst) {
    const char* kg = reinterpret_cast<const char*>(g_kf) + (size_t)t * 32768;
    const char* vg = reinterpret_cast<const char*>(g_vf) + (size_t)t * 32768;
#pragma unroll
    for (int u = 0; u < 8; u++) {
        int id = u * 256 + tid;
        cp16(sb + kdst + id * 16, kg + id * 16);
    }
#pragma unroll
    for (int u = 0; u < 8; u++) {
        int id = u * 256 + tid;
        cp16(sb + vdst + id * 16, vg + id * 16);
    }
}

// ---------------------------------------------------------------------------
// Prep: per key row, write tf32 values into fragment-packed global layouts.
// KF elem addr: t*8192 + ng*4096 + s*256 + j*128 + (4g+tig)*4 + np*2 + h
//   where key = 64t + 32ng + 8(2j+np) + g,  d-col c = 8s + tig + 4h
// VF elem addr: t*8192 + ng*4096 + sv*1024 + j*128 + (4g+tv)*4 + np*2 + hv
//   where key = 64t + 32ng + 8sv + tv + 4hv,  d-col c = 8(2j+np) + g
// ---------------------------------------------------------------------------
__global__ void prep_kernel(const float* __restrict__ keys, int K) {
    int row = blockIdx.x * blockDim.y + threadIdx.y;
    if (row >= K) return;
    int lane = threadIdx.x;
    float4 v = reinterpret_cast<const float4*>(keys + (size_t)row * D)[lane];
    float ss = v.x * v.x + v.y * v.y + v.z * v.z + v.w * v.w;
#pragma unroll
    for (int o = 16; o; o >>= 1) ss += __shfl_xor_sync(0xffffffffu, ss, o);
    float s = 1.0f / fmaxf(sqrtf(ss), 1e-12f);

    int t = row >> 6, kt = row & 63;
    int ng = kt >> 5, r5 = kt & 31;
    int ntk = r5 >> 3, gk = r5 & 7;                 // score-side key decomp
    size_t kb = (size_t)t * 8192 + ng * 4096 + (ntk >> 1) * 128 + ((ntk & 1) << 1);
    int sv = r5 >> 3, tv = r5 & 3, hv = (r5 >> 2) & 1;   // value-side key decomp
    size_t vb = (size_t)t * 8192 + ng * 4096 + sv * 1024 + hv;

    float vals[4] = {v.x, v.y, v.z, v.w};
#pragma unroll
    for (int c4 = 0; c4 < 4; c4++) {
        int c = 4 * lane + c4;
        int sK = c >> 3, tigK = c & 3, hK = (c >> 2) & 1;
        g_kf[kb + sK * 256 + (4 * gk + tigK) * 4 + hK] = to_tf32f(vals[c4] * s);
        int ntv = c >> 3, gv = c & 7;
        g_vf[vb + (ntv >> 1) * 128 + (4 * gv + tv) * 4 + ((ntv & 1) << 1)] = to_tf32f(vals[c4]);
    }
}

// ---------------------------------------------------------------------------
// Fused flash kernel: 128 queries/CTA, tf32 mma.sync, fragment-packed LDS.128.
// ---------------------------------------------------------------------------
__global__ __launch_bounds__(256, 1)
void fused_mma(const float* __restrict__ queries, float* __restrict__ out, int K) {
    extern __shared__ __align__(16) float sm[];
    const uint32_t sb = smem_u32(sm);
    const int tid  = threadIdx.x;
    const int w    = tid >> 5;
    const int lane = tid & 31;
    const int g    = lane >> 2;
    const int tig  = lane & 3;
    const int mg   = w >> 1;         // 0..3 : 32-row stripe
    const int ng   = w & 1;          // 0..1 : 32-key chunk within tile
    const int q0   = blockIdx.x * TQ;
    const int niter = K / TK;

    // ---- prologue: tile 0 ----
    load_tile(sb, tid, 0, SM_K0, SM_V0);
    cp_commit();

    // ---- Q: load, normalize, tf32, to Qtmp[row][c] (stride 132) ----
    float* Qt = sm + SM_QT / 4;
    {
        int row  = tid >> 1;
        int part = tid & 1;
        const float4* qr = reinterpret_cast<const float4*>(
            queries + (size_t)(q0 + row) * D + part * 64);
        float ss = 0.f;
#pragma unroll
        for (int i = 0; i < 16; i++) {
            float4 v = qr[i];
            ss += v.x * v.x + v.y * v.y + v.z * v.z + v.w * v.w;
        }
        ss += __shfl_xor_sync(0xffffffffu, ss, 1);
        float s = 1.0f / fmaxf(sqrtf(ss), 1e-12f);
        float* qd = Qt + row * 132 + part * 64;
#pragma unroll
        for (int i = 0; i < 16; i++) {
            float4 v = qr[i];
            *reinterpret_cast<float4*>(qd + i * 4) =
                make_float4(to_tf32f(v.x * s), to_tf32f(v.y * s),
                            to_tf32f(v.z * s), to_tf32f(v.w * s));
        }
    }
    __syncthreads();

    // ---- pack QF: warp (mg, mt=ng) packs its 16 s-blocks ----
    {
        int R = 32 * mg + 16 * ng;
        float* dst = sm + (mg * 2 + ng) * 2048 + lane * 4;
#pragma unroll
        for (int s = 0; s < 16; s++) {
            int C = 8 * s + tig;
            float a0 = Qt[(R + g) * 132 + C];
            float a1 = Qt[(R + g + 8) * 132 + C];
            float a2 = Qt[(R + g) * 132 + C + 4];
            float a3 = Qt[(R + g + 8) * 132 + C + 4];
            *reinterpret_cast<float4*>(dst + s * 128) = make_float4(a0, a1, a2, a3);
        }
    }

    const float* qA = sm + (mg * 2) * 2048 + lane * 4;   // mt stride = 2048 floats

    float Oa[32][4];
#pragma unroll
    for (int i = 0; i < 32; i++)
#pragma unroll
        for (int j = 0; j < 4; j++) Oa[i][j] = 0.f;
    float dacc[4] = {0.f, 0.f, 0.f, 0.f};

    const int src_a = (lane & 28) | (tig >> 1);
    const int src_b = src_a + 2;
    const bool odd  = (tig & 1);

    for (int it = 0; it < niter; it++) {
        cp_wait0();
        __syncthreads();               // tile it visible; buffers of it-1 free

        if (it + 1 < niter)
            load_tile(sb, tid, it + 1,
                      ((it + 1) & 1) ? SM_K1 : SM_K0,
                      ((it + 1) & 1) ? SM_V1 : SM_V0);
        cp_commit();

        const float* Ksb = sm + (((it & 1) ? SM_K1 : SM_K0) >> 2) + ng * 4096 + lane * 4;
        const float* Vsb = sm + (((it & 1) ? SM_V1 : SM_V0) >> 2) + ng * 4096 + lane * 4;

        // ---- GEMM1: S(32x32) = Qn . Kn^T ----
        float Sa[8][4];
#pragma unroll
        for (int i = 0; i < 8; i++)
#pragma unroll
            for (int j = 0; j < 4; j++) Sa[i][j] = 0.f;
#pragma unroll
        for (int s = 0; s < 16; s++) {
            float4 A0 = *reinterpret_cast<const float4*>(qA + s * 128);
            float4 A1 = *reinterpret_cast<const float4*>(qA + 2048 + s * 128);
            float4 B0 = *reinterpret_cast<const float4*>(Ksb + s * 256);
            float4 B1 = *reinterpret_cast<const float4*>(Ksb + s * 256 + 128);
            MMA8F(Sa[0], A0, B0.x, B0.y);
            MMA8F(Sa[4], A1, B0.x, B0.y);
            MMA8F(Sa[1], A0, B0.z, B0.w);
            MMA8F(Sa[5], A1, B0.z, B0.w);
            MMA8F(Sa[2], A0, B1.x, B1.y);
            MMA8F(Sa[6], A1, B1.x, B1.y);
            MMA8F(Sa[3], A0, B1.z, B1.w);
            MMA8F(Sa[7], A1, B1.z, B1.w);
        }

        // ---- softmax in registers (cosine scores => no max pass) ----
#pragma unroll
        for (int mt = 0; mt < 2; mt++)
#pragma unroll
            for (int nt = 0; nt < 4; nt++) {
                float* f = Sa[mt * 4 + nt];
#pragma unroll
                for (int e = 0; e < 4; e++) {
                    float p = __expf(f[e]);
                    dacc[mt * 2 + (e >> 1)] += p;
                    f[e] = to_tf32f(p);
                }
            }

        // ---- GEMM2: O(32x128 private) += P(regs) . V ----
#pragma unroll
        for (int s = 0; s < 4; s++) {
            float4 A[2];
#pragma unroll
            for (int mt = 0; mt < 2; mt++) {
                const float* dreg = Sa[mt * 4 + s];
                float x0 = __shfl_sync(0xffffffffu, dreg[0], src_a);
                float x1 = __shfl_sync(0xffffffffu, dreg[1], src_a);
                float x2 = __shfl_sync(0xffffffffu, dreg[2], src_a);
                float x3 = __shfl_sync(0xffffffffu, dreg[3], src_a);
                float y0 = __shfl_sync(0xffffffffu, dreg[0], src_b);
                float y1 = __shfl_sync(0xffffffffu, dreg[1], src_b);
                float y2 = __shfl_sync(0xffffffffu, dreg[2], src_b);
                float y3 = __shfl_sync(0xffffffffu, dreg[3], src_b);
                A[mt] = make_float4(odd ? x1 : x0, odd ? x3 : x2,
                                    odd ? y1 : y0, odd ? y3 : y2);
            }
            const float* vb = Vsb + s * 1024;
#pragma unroll
            for (int j = 0; j < 8; j++) {
                float4 Bf = *reinterpret_cast<const float4*>(vb + j * 128);
                MMA8F(Oa[2 * j],          A[0], Bf.x, Bf.y);
                MMA8F(Oa[16 + 2 * j],     A[1], Bf.x, Bf.y);
                MMA8F(Oa[2 * j + 1],      A[0], Bf.z, Bf.w);
                MMA8F(Oa[16 + 2 * j + 1], A[1], Bf.z, Bf.w);
            }
        }
    }

    __syncthreads();   // loop done; QF/K0 regions free for epilogue exchange

    float* DS = sm + SM_DS / 4;

    // ---- denominators ----
#pragma unroll
    for (int r = 0; r < 4; r++) {
        dacc[r] += __shfl_xor_sync(0xffffffffu, dacc[r], 1);
        dacc[r] += __shfl_xor_sync(0xffffffffu, dacc[r], 2);
    }
    if (tig == 0) {
#pragma unroll
        for (int r = 0; r < 4; r++) {
            int row = 32 * mg + 16 * (r >> 1) + g + ((r & 1) << 3);
            DS[ng * 128 + row] = dacc[r];
        }
    }

    // ---- O pair-reduction: ng=0 publishes, ng=1 combines + writes ----
    float* Eb = sm + mg * 4224 + lane * 132;
    if (ng == 0) {
#pragma unroll
        for (int j = 0; j < 32; j++)
            *reinterpret_cast<float4*>(Eb + j * 4) =
                *reinterpret_cast<const float4*>(Oa[j]);
    }
    __syncthreads();

    if (ng == 1) {
#pragma unroll
        for (int mt = 0; mt < 2; mt++) {
            int row0 = 32 * mg + 16 * mt + g;
            float i0 = 1.0f / (DS[row0] + DS[128 + row0]);
            float i1 = 1.0f / (DS[row0 + 8] + DS[128 + row0 + 8]);
#pragma unroll
            for (int nt = 0; nt < 16; nt++) {
                int j = mt * 16 + nt;
                float4 p = *reinterpret_cast<const float4*>(Eb + j * 4);
                float2 o0 = make_float2((Oa[j][0] + p.x) * i0,
                                        (Oa[j][1] + p.y) * i0);
                float2 o1 = make_float2((Oa[j][2] + p.z) * i1,
                                        (Oa[j][3] + p.w) * i1);
                float* base = out + (size_t)(q0 + row0) * D + 8 * nt + 2 * tig;
                *reinterpret_cast<float2*>(base)         = o0;
                *reinterpret_cast<float2*>(base + 8 * D) = o1;
            }
        }
    }
}

// ---------------------------------------------------------------------------
extern "C" void kernel_launch(void* const* d_in, const int* in_sizes, int n_in,
                              void* d_out, int out_size) {
    const float* queries = (const float*)d_in[0];
    const float* keys    = (const float*)d_in[1];
    float*       out     = (float*)d_out;

    int N = in_sizes[0] / D;
    int K = in_sizes[1] / D;

    cudaFuncSetAttribute(fused_mma, cudaFuncAttributeMaxDynamicSharedMemorySize, SMEM_TOTAL);

    prep_kernel<<<(K + 7) / 8, dim3(32, 8)>>>(keys, K);
    fused_mma<<<N / TQ, 256, SMEM_TOTAL>>>(queries, out, K);
}

// round 8
// speedup vs baseline: 5.3492x; 1.0686x over previous
#include <cuda_runtime.h>
#include <cstdint>
#include <math.h>

#define D    128
#define TQ   128
#define TK   64
#define KMAX 4096
#define NMAX 65536
#define NT64 (KMAX / 64)

// Fragment-packed operands in global (written by prep kernels, tf32-rounded):
// g_kf: [tile][ng(2)][s(16)][j(2)][lane(32)][4]  normalized keys (score side)
// g_vf: [tile][ng(2)][sv(4)][j(8)][lane(32)][4]  raw keys (value side)
// g_qf: [cta][slot(8)][s(16)][lane(32)][4]       normalized queries
__device__ __align__(16) float g_kf[(size_t)NT64 * 8192];
__device__ __align__(16) float g_vf[(size_t)NT64 * 8192];
__device__ __align__(16) float g_qf[(size_t)(NMAX / TQ) * 16384];

// SMEM layout (bytes): QF | per-group double-buffered K/V chunks | DS
#define SM_QF  0            // 65536
#define SM_GRP 65536        // group ng base = SM_GRP + ng*65536; buf b at +b*32768 (K), +16384 (V)
#define SM_DS  196608       // 1024
#define SMEM_TOTAL 197632

// ---------------- helpers ----------------
__device__ __forceinline__ uint32_t smem_u32(const void* p) {
    uint32_t a;
    asm("{ .reg .u64 t; cvta.to.shared.u64 t, %1; cvt.u32.u64 %0, t; }" : "=r"(a) : "l"(p));
    return a;
}
__device__ __forceinline__ void cp16(uint32_t s, const void* g) {
    asm volatile("cp.async.cg.shared.global [%0], [%1], 16;\n" :: "r"(s), "l"(g));
}
__device__ __forceinline__ void cp_commit() { asm volatile("cp.async.commit_group;\n" ::: "memory"); }
__device__ __forceinline__ void cp_wait0()  { asm volatile("cp.async.wait_group 0;\n" ::: "memory"); }
__device__ __forceinline__ void group_bar(int id) {
    asm volatile("bar.sync %0, %1;" :: "r"(id), "r"(128) : "memory");
}

__device__ __forceinline__ uint32_t to_tf32(float f) {
    uint32_t r;
    asm("cvt.rna.tf32.f32 %0, %1;" : "=r"(r) : "f"(f));
    return r;
}
__device__ __forceinline__ float to_tf32f(float f) { return __uint_as_float(to_tf32(f)); }

__device__ __forceinline__ void mma8(float* d,
                                     uint32_t a0, uint32_t a1, uint32_t a2, uint32_t a3,
                                     uint32_t b0, uint32_t b1) {
    asm volatile(
        "mma.sync.aligned.m16n8k8.row.col.f32.tf32.tf32.f32 "
        "{%0,%1,%2,%3},{%4,%5,%6,%7},{%8,%9},{%0,%1,%2,%3};\n"
        : "+f"(d[0]), "+f"(d[1]), "+f"(d[2]), "+f"(d[3])
        : "r"(a0), "r"(a1), "r"(a2), "r"(a3), "r"(b0), "r"(b1));
}
#define MMA8F(dst, A, b0, b1) \
    mma8(dst, __float_as_uint((A).x), __float_as_uint((A).y), \
              __float_as_uint((A).z), __float_as_uint((A).w), \
              __float_as_uint(b0), __float_as_uint(b1))

// Group tile chunk: 16KB K + 16KB V, loaded by the group's 128 threads (tg = tid&127)
__device__ __forceinline__ void load_group(uint32_t sb, int tg, int t, int ng) {
    const char* kg = reinterpret_cast<const char*>(g_kf) + (size_t)t * 32768 + ng * 16384;
    const char* vg = reinterpret_cast<const char*>(g_vf) + (size_t)t * 32768 + ng * 16384;
    const uint32_t kdst = SM_GRP + ng * 65536 + (t & 1) * 32768;
    const uint32_t vdst = kdst + 16384;
#pragma unroll
    for (int u = 0; u < 8; u++) {
        int id = u * 128 + tg;
        cp16(kdst + sb + id * 16, kg + id * 16);
    }
#pragma unroll
    for (int u = 0; u < 8; u++) {
        int id = u * 128 + tg;
        cp16(vdst + sb + id * 16, vg + id * 16);
    }
}

// ---------------------------------------------------------------------------
// Key prep: normalized (score) + raw (value) copies, tf32, fragment-packed.
// ---------------------------------------------------------------------------
__global__ void prep_kernel(const float* __restrict__ keys, int K) {
    int row = blockIdx.x * blockDim.y + threadIdx.y;
    if (row >= K) return;
    int lane = threadIdx.x;
    float4 v = reinterpret_cast<const float4*>(keys + (size_t)row * D)[lane];
    float ss = v.x * v.x + v.y * v.y + v.z * v.z + v.w * v.w;
#pragma unroll
    for (int o = 16; o; o >>= 1) ss += __shfl_xor_sync(0xffffffffu, ss, o);
    float s = 1.0f / fmaxf(sqrtf(ss), 1e-12f);

    int t = row >> 6, kt = row & 63;
    int ng = kt >> 5, r5 = kt & 31;
    int ntk = r5 >> 3, gk = r5 & 7;
    size_t kb = (size_t)t * 8192 + ng * 4096 + (ntk >> 1) * 128 + ((ntk & 1) << 1);
    int sv = r5 >> 3, tv = r5 & 3, hv = (r5 >> 2) & 1;
    size_t vb = (size_t)t * 8192 + ng * 4096 + sv * 1024 + hv;

    float vals[4] = {v.x, v.y, v.z, v.w};
#pragma unroll
    for (int c4 = 0; c4 < 4; c4++) {
        int c = 4 * lane + c4;
        int sK = c >> 3, tigK = c & 3, hK = (c >> 2) & 1;
        g_kf[kb + sK * 256 + (4 * gk + tigK) * 4 + hK] = to_tf32f(vals[c4] * s);
        int ntv = c >> 3, gv = c & 7;
        g_vf[vb + (ntv >> 1) * 128 + (4 * gv + tv) * 4 + ((ntv & 1) << 1)] = to_tf32f(vals[c4]);
    }
}

// ---------------------------------------------------------------------------
// Query prep: normalize, tf32, write A-fragment-packed per CTA.
// Element (row, col): cta=row>>7, r=row&127: mg=r>>5, mt=(r>>4)&1, h=(r>>3)&1,
// g=r&7; col: s=c>>3, tig=c&3, chi=(c>>2)&1.
// addr = cta*16384 + (2mg+mt)*2048 + s*128 + (4g+tig)*4 + h + 2*chi
// ---------------------------------------------------------------------------
__global__ void prep_q(const float* __restrict__ queries, int N) {
    int row = blockIdx.x * blockDim.y + threadIdx.y;
    if (row >= N) return;
    int lane = threadIdx.x;
    float4 v = reinterpret_cast<const float4*>(queries + (size_t)row * D)[lane];
    float ss = v.x * v.x + v.y * v.y + v.z * v.z + v.w * v.w;
#pragma unroll
    for (int o = 16; o; o >>= 1) ss += __shfl_xor_sync(0xffffffffu, ss, o);
    float s = 1.0f / fmaxf(sqrtf(ss), 1e-12f);

    int cta = row >> 7, r = row & 127;
    int mg = r >> 5, mt = (r >> 4) & 1, h = (r >> 3) & 1, g = r & 7;
    size_t base = (size_t)cta * 16384 + (2 * mg + mt) * 2048 + g * 16 + h;

    float vals[4] = {v.x, v.y, v.z, v.w};
#pragma unroll
    for (int c4 = 0; c4 < 4; c4++) {
        int c = 4 * lane + c4;
        int sQ = c >> 3, tig = c & 3, chi = (c >> 2) & 1;
        g_qf[base + sQ * 128 + tig * 4 + 2 * chi] = to_tf32f(vals[c4] * s);
    }
}

// ---------------------------------------------------------------------------
// Fused flash kernel: 128 queries/CTA; two decoupled 4-warp pipelines.
// ---------------------------------------------------------------------------
__global__ __launch_bounds__(256, 1)
void fused_mma(float* __restrict__ out, int K) {
    extern __shared__ __align__(16) float sm[];
    const uint32_t sb = smem_u32(sm);
    const int tid  = threadIdx.x;
    const int w    = tid >> 5;
    const int lane = tid & 31;
    const int g    = lane >> 2;
    const int tig  = lane & 3;
    const int ng   = w >> 2;         // group: 0 or 1 (warps 0-3 / 4-7)
    const int mg   = w & 3;          // 32-row stripe within group
    const int tg   = tid & 127;
    const int q0   = blockIdx.x * TQ;
    const int niter = K / TK;

    // ---- prologue: QF (all threads) + group tile 0 ----
    {
        const char* qg = reinterpret_cast<const char*>(g_qf) + (size_t)blockIdx.x * 65536;
#pragma unroll
        for (int u = 0; u < 16; u++) {
            int id = u * 256 + tid;
            cp16(sb + SM_QF + id * 16, qg + id * 16);
        }
        load_group(sb, tg, 0, ng);
        cp_commit();
        cp_wait0();
    }
    __syncthreads();

    const float* qA = sm + (mg * 2) * 2048 + lane * 4;   // mt stride = 2048 floats

    float Oa[32][4];
#pragma unroll
    for (int i = 0; i < 32; i++)
#pragma unroll
        for (int j = 0; j < 4; j++) Oa[i][j] = 0.f;
    float dacc[4] = {0.f, 0.f, 0.f, 0.f};

    const int src_a = (lane & 28) | (tig >> 1);
    const int src_b = src_a + 2;
    const bool odd  = (tig & 1);

    for (int it = 0; it < niter; it++) {
        if (it + 1 < niter) {          // prefetch next group chunk
            load_group(sb, tg, it + 1, ng);
            cp_commit();
        }

        const float* Ksb = sm + ((SM_GRP + ng * 65536 + (it & 1) * 32768) >> 2) + lane * 4;
        const float* Vsb = Ksb + 4096;

        // ---- GEMM1: S(32x32) = Qn . Kn^T ----
        float Sa[8][4];
#pragma unroll
        for (int i = 0; i < 8; i++)
#pragma unroll
            for (int j = 0; j < 4; j++) Sa[i][j] = 0.f;
#pragma unroll
        for (int s = 0; s < 16; s++) {
            float4 A0 = *reinterpret_cast<const float4*>(qA + s * 128);
            float4 A1 = *reinterpret_cast<const float4*>(qA + 2048 + s * 128);
            float4 B0 = *reinterpret_cast<const float4*>(Ksb + s * 256);
            float4 B1 = *reinterpret_cast<const float4*>(Ksb + s * 256 + 128);
            MMA8F(Sa[0], A0, B0.x, B0.y);
            MMA8F(Sa[4], A1, B0.x, B0.y);
            MMA8F(Sa[1], A0, B0.z, B0.w);
            MMA8F(Sa[5], A1, B0.z, B0.w);
            MMA8F(Sa[2], A0, B1.x, B1.y);
            MMA8F(Sa[6], A1, B1.x, B1.y);
            MMA8F(Sa[3], A0, B1.z, B1.w);
            MMA8F(Sa[7], A1, B1.z, B1.w);
        }

        // ---- softmax in registers (cosine scores => no max pass) ----
#pragma unroll
        for (int mt = 0; mt < 2; mt++)
#pragma unroll
            for (int nt = 0; nt < 4; nt++) {
                float* f = Sa[mt * 4 + nt];
#pragma unroll
                for (int e = 0; e < 4; e++) {
                    float p = __expf(f[e]);
                    dacc[mt * 2 + (e >> 1)] += p;
                    f[e] = to_tf32f(p);
                }
            }

        // ---- GEMM2: O(32x128 private) += P(regs) . V ----
#pragma unroll
        for (int s = 0; s < 4; s++) {
            float4 A[2];
#pragma unroll
            for (int mt = 0; mt < 2; mt++) {
                const float* dreg = Sa[mt * 4 + s];
                float x0 = __shfl_sync(0xffffffffu, dreg[0], src_a);
                float x1 = __shfl_sync(0xffffffffu, dreg[1], src_a);
                float x2 = __shfl_sync(0xffffffffu, dreg[2], src_a);
                float x3 = __shfl_sync(0xffffffffu, dreg[3], src_a);
                float y0 = __shfl_sync(0xffffffffu, dreg[0], src_b);
                float y1 = __shfl_sync(0xffffffffu, dreg[1], src_b);
                float y2 = __shfl_sync(0xffffffffu, dreg[2], src_b);
                float y3 = __shfl_sync(0xffffffffu, dreg[3], src_b);
                A[mt] = make_float4(odd ? x1 : x0, odd ? x3 : x2,
                                    odd ? y1 : y0, odd ? y3 : y2);
            }
            const float* vb = Vsb + s * 1024;
#pragma unroll
            for (int j = 0; j < 8; j++) {
                float4 Bf = *reinterpret_cast<const float4*>(vb + j * 128);
                MMA8F(Oa[2 * j],          A[0], Bf.x, Bf.y);
                MMA8F(Oa[16 + 2 * j],     A[1], Bf.x, Bf.y);
                MMA8F(Oa[2 * j + 1],      A[0], Bf.z, Bf.w);
                MMA8F(Oa[16 + 2 * j + 1], A[1], Bf.z, Bf.w);
            }
        }

        if (it + 1 < niter) {
            cp_wait0();                // next tile landed
            group_bar(ng + 1);         // group-local visibility + buffer retire
        }
    }

    __syncthreads();   // join both groups; QF region free for epilogue exchange

    float* DS = sm + SM_DS / 4;

    // ---- denominators ----
#pragma unroll
    for (int r = 0; r < 4; r++) {
        dacc[r] += __shfl_xor_sync(0xffffffffu, dacc[r], 1);
        dacc[r] += __shfl_xor_sync(0xffffffffu, dacc[r], 2);
    }
    if (tig == 0) {
#pragma unroll
        for (int r = 0; r < 4; r++) {
            int row = 32 * mg + 16 * (r >> 1) + g + ((r & 1) << 3);
            DS[ng * 128 + row] = dacc[r];
        }
    }

    // ---- O pair-reduction: ng=0 publishes, ng=1 combines + writes ----
    float* Eb = sm + mg * 4224 + lane * 132;
    if (ng == 0) {
#pragma unroll
        for (int j = 0; j < 32; j++)
            *reinterpret_cast<float4*>(Eb + j * 4) =
                *reinterpret_cast<const float4*>(Oa[j]);
    }
    __syncthreads();

    if (ng == 1) {
#pragma unroll
        for (int mt = 0; mt < 2; mt++) {
            int row0 = 32 * mg + 16 * mt + g;
            float i0 = 1.0f / (DS[row0] + DS[128 + row0]);
            float i1 = 1.0f / (DS[row0 + 8] + DS[128 + row0 + 8]);
#pragma unroll
            for (int nt = 0; nt < 16; nt++) {
                int j = mt * 16 + nt;
                float4 p = *reinterpret_cast<const float4*>(Eb + j * 4);
                float2 o0 = make_float2((Oa[j][0] + p.x) * i0,
                                        (Oa[j][1] + p.y) * i0);
                float2 o1 = make_float2((Oa[j][2] + p.z) * i1,
                                        (Oa[j][3] + p.w) * i1);
                float* base = out + (size_t)(q0 + row0) * D + 8 * nt + 2 * tig;
                *reinterpret_cast<float2*>(base)         = o0;
                *reinterpret_cast<float2*>(base + 8 * D) = o1;
            }
        }
    }
}

// ---------------------------------------------------------------------------
extern "C" void kernel_launch(void* const* d_in, const int* in_sizes, int n_in,
                              void* d_out, int out_size) {
    const float* queries = (const float*)d_in[0];
    const float* keys    = (const float*)d_in[1];
    float*       out     = (float*)d_out;

    int N = in_sizes[0] / D;
    int K = in_sizes[1] / D;

    cudaFuncSetAttribute(fused_mma, cudaFuncAttributeMaxDynamicSharedMemorySize, SMEM_TOTAL);

    prep_kernel<<<(K + 7) / 8, dim3(32, 8)>>>(keys, K);
    prep_q<<<(N + 7) / 8, dim3(32, 8)>>>(queries, N);
    fused_mma<<<N / TQ, 256, SMEM_TOTAL>>>(out, K);
}